// round 15
// baseline (speedup 1.0000x reference)
#include <cuda_runtime.h>
#include <cuda.h>
#include <cuda_fp16.h>
#include <cstdint>

// ---------------------------------------------------------------------------
// FeatherNet, ONE mega-launch containing prep + all 4 GEMMs, chained by
// device-side release/acquire counters:
//   prep0: V1 f32->f16 pad      (5794 blocks)   releases g_pA[46]
//   prep1: V2 transpose->f16    (16744, nb-major) releases g_pB[46]
//   prep2: x f32->f16           (8192 blocks)   releases g_pX
//   seg0:  Vf = V1h@V2T^T (2116)  waits pA[by], pB[bx]
//   seg1:  h1 (1024)  waits g_cA(W1 rows of Vf) + g_pX
//   seg2:  h2 (1024)  waits g_cB + its h1 row block
//   seg3:  out (512)  waits g_cC + its h2 row block
// GEMM body: TMA + mbarrier ring + ldmatrix + mma.sync fp16, cross-stage
// fragment pipelining (R13).
// ---------------------------------------------------------------------------

#define SIZE_N 5794
#define SIZE_M 2897
#define K_PAD  2944        // 46 * 64
#define BATCH  4096
#define D_IN   2048
#define D_H    4096
#define D_OUT  2048

#define OFF_W1 0
#define OFF_B1 8388608
#define OFF_W2 8392704
#define OFF_B2 25169920
#define OFF_W3 25174016
#define OFF_B3 33562624

#define G0_CTAS 2116       // 46 x 46
#define L1_CTAS 1024       // 32 x 32
#define L2_CTAS 1024
#define L3_CTAS 512        // 32 by x 16 bx
#define TGT_A   552        // 12 Vf row-tiles x 46 (covers W1+b1)
#define TGT_B   1564       // 34 Vf row-tiles x 46 (covers W2+b2)

// prep segmentation (blockDim = 128)
#define P_V1   SIZE_N                     // one V1 row per block
#define TRN_NB 182                        // ceil(5794/32) n-tiles
#define TRN_KB (K_PAD / 32)               // 92 k-tiles
#define P_V2   (TRN_NB * TRN_KB)          // 16744, nb-major order
#define P_X    (BATCH * D_IN / 8 / 128)   // 8192 blocks, 8 f32/thread
#define PREP_TOT (P_V1 + P_V2 + P_X)      // 30730

__device__ __align__(256) __half g_V1h[(size_t)SIZE_N * K_PAD];
__device__ __align__(256) __half g_V2T[(size_t)SIZE_N * K_PAD];
__device__ __align__(256) __half g_xh [(size_t)BATCH * D_IN];
__device__ __align__(256) __half g_Vf [(size_t)SIZE_N * SIZE_N];
__device__ __align__(256) __half g_h1 [(size_t)BATCH * D_H];
__device__ __align__(256) __half g_h2 [(size_t)BATCH * D_H];

__device__ uint32_t g_cA, g_cB, g_cC;
__device__ uint32_t g_c1r[32], g_c2r[32];
__device__ uint32_t g_pA[46], g_pB[46], g_pX;

// ============================ PTX helpers ===================================

__device__ __forceinline__ uint32_t smem_u32(const void* p) {
    uint32_t a;
    asm("{ .reg .u64 t; cvta.to.shared.u64 t, %1; cvt.u32.u64 %0, t; }"
        : "=r"(a) : "l"(p));
    return a;
}

#define MBARRIER_INIT(addr, cnt) \
    asm volatile("mbarrier.init.shared.b64 [%0], %1;" \
                 :: "r"((uint32_t)(addr)), "r"((uint32_t)(cnt)) : "memory")

#define MBARRIER_EXPECT_TX(addr, bytes) \
    asm volatile("mbarrier.arrive.expect_tx.shared.b64 _, [%0], %1;" \
                 :: "r"((uint32_t)(addr)), "r"((uint32_t)(bytes)) : "memory")

#define MBARRIER_ARRIVE(addr) \
    asm volatile("mbarrier.arrive.shared.b64 _, [%0];" \
                 :: "r"((uint32_t)(addr)) : "memory")

#define MBARRIER_WAIT_PARITY(addr, par) do {                                         \
    uint32_t _m = (uint32_t)(addr); uint32_t _p = (uint32_t)(par); uint32_t _d;      \
    asm volatile("{\n\t.reg .pred p;\n\t"                                            \
        "mbarrier.try_wait.parity.acquire.cta.shared::cta.b64 p, [%1], %2;\n\t"      \
        "selp.b32 %0, 1, 0, p;\n\t}"                                                 \
        : "=r"(_d) : "r"(_m), "r"(_p) : "memory");                                   \
    if (!_d) {                                                                       \
        asm volatile("{\n\t.reg .pred P1;\n\t"                                       \
            "WL_%=:\n\t"                                                             \
            "mbarrier.try_wait.parity.acquire.cta.shared::cta.b64 P1, [%0], %1, 0x989680;\n\t" \
            "@P1 bra.uni WD_%=;\n\t"                                                 \
            "bra.uni WL_%=;\n\t"                                                     \
            "WD_%=:\n\t}"                                                            \
            :: "r"(_m), "r"(_p) : "memory");                                         \
    }                                                                                \
} while (0)

__device__ __forceinline__ void tma2d(uint32_t dst, const CUtensorMap* m,
                                      int cx, int cy, uint32_t bar) {
    asm volatile(
        "cp.async.bulk.tensor.2d.shared::cta.global.tile.mbarrier::complete_tx::bytes "
        "[%0], [%1, {%2, %3}], [%4];"
        :: "r"(dst), "l"(m), "r"(cx), "r"(cy), "r"(bar) : "memory");
}

__device__ __forceinline__ void mma_f16(float4& d, const uint32_t* a, const uint32_t* b) {
    asm volatile(
        "mma.sync.aligned.m16n8k16.row.col.f32.f16.f16.f32 "
        "{%0,%1,%2,%3}, {%4,%5,%6,%7}, {%8,%9}, {%0,%1,%2,%3};"
        : "+f"(d.x), "+f"(d.y), "+f"(d.z), "+f"(d.w)
        : "r"(a[0]), "r"(a[1]), "r"(a[2]), "r"(a[3]), "r"(b[0]), "r"(b[1]));
}

__device__ __forceinline__ void ldsm_x4(uint32_t* r, uint32_t addr) {
    asm volatile("ldmatrix.sync.aligned.m8n8.x4.shared.b16 {%0,%1,%2,%3}, [%4];"
                 : "=r"(r[0]), "=r"(r[1]), "=r"(r[2]), "=r"(r[3]) : "r"(addr));
}

__device__ __forceinline__ uint32_t ld_acq(const uint32_t* p) {
    uint32_t v;
    asm volatile("ld.acquire.gpu.u32 %0, [%1];" : "=r"(v) : "l"(p) : "memory");
    return v;
}
__device__ __forceinline__ void red_rel(uint32_t* p) {
    asm volatile("red.release.gpu.add.u32 [%0], 1;" :: "l"(p) : "memory");
}
__device__ __forceinline__ void spinc(const uint32_t* p, uint32_t tgt) {
    while (ld_acq(p) < tgt) __nanosleep(128);
}
#define FENCE_PROXY_ASYNC() asm volatile("fence.proxy.async;" ::: "memory")

// ============================ GEMM body =====================================

#define NST 3
#define STAGE_BYTES 32768
#define SMEM_REQ 99392

template<bool BIAS, bool RELU, typename CT>
__device__ __forceinline__ void gemm_body(
    uint32_t* smu,
    const CUtensorMap* tmA, const CUtensorMap* tmB,
    const __half* __restrict__ bias, CT* __restrict__ C,
    int M, int N, int T, int ldc, int bx, int by)
{
    const uint32_t sbr = smem_u32(smu);
    const uint32_t st0 = (sbr + 48 + 1023) & ~1023u;

    const int tid = threadIdx.x;
    const int wid = tid >> 5;
    const int lid = tid & 31;
    const int r   = lid >> 2;
    const int c   = lid & 3;
    const int bm  = by * 128;
    const int bn  = bx * 128;
    const int m0  = (wid & 1) * 64;
    const int n0  = (wid >> 1) * 64;

    if (tid == 0) {
#pragma unroll
        for (int s = 0; s < NST; s++) {
            MBARRIER_INIT(sbr + 16 * s, 1);
            MBARRIER_INIT(sbr + 16 * s + 8, 128);
        }
    }
    __syncthreads();

    const int e    = lid & 7;
    const uint32_t aRowB = (uint32_t)(m0 + ((lid >> 3) & 1) * 8 + e) * 128;
    const uint32_t bRowB = (uint32_t)(n0 + (lid >> 4) * 8 + e) * 128;
    uint32_t xa[4], xb[4];
#pragma unroll
    for (int kc = 0; kc < 4; kc++) {
        xa[kc] = (uint32_t)((((2 * kc + (lid >> 4)) ^ e) & 7) * 16);
        xb[kc] = (uint32_t)((((2 * kc + ((lid >> 3) & 1)) ^ e) & 7) * 16);
    }

    float4 acc[4][8];
#pragma unroll
    for (int i = 0; i < 4; i++)
#pragma unroll
        for (int j = 0; j < 8; j++) acc[i][j] = make_float4(0.f, 0.f, 0.f, 0.f);

    if (tid == 0) {
        int npro = T < 2 ? T : 2;
        for (int p = 0; p < npro; p++) {
            MBARRIER_EXPECT_TX(sbr + 16 * p, STAGE_BYTES);
            tma2d(st0 + p * STAGE_BYTES,         tmA, p * 64, bm, sbr + 16 * p);
            tma2d(st0 + p * STAGE_BYTES + 16384, tmB, p * 64, bn, sbr + 16 * p);
        }
    }

    uint32_t fa[2][4][4], fb[2][4][4];

    int s = 0, fph = 0;
    int s2 = 2, eph = 1;

    MBARRIER_WAIT_PARITY(sbr + 0, 0);
    {
        const uint32_t sA = st0, sB = st0 + 16384;
        ldsm_x4(fa[0][0], sA + aRowB + xa[0]);
#pragma unroll
        for (int jp = 0; jp < 4; jp++) ldsm_x4(fb[0][jp], sB + bRowB + jp * 2048 + xb[0]);
#pragma unroll
        for (int i = 1; i < 4; i++)   ldsm_x4(fa[0][i], sA + aRowB + i * 2048 + xa[0]);
    }

    for (int t = 0; t < T; t++) {
        const uint32_t sA = st0 + (uint32_t)s * STAGE_BYTES;
        const uint32_t sB = sA + 16384;

        if (tid == 0 && t + 2 < T) {
            MBARRIER_WAIT_PARITY(sbr + 16 * s2 + 8, eph);
            MBARRIER_EXPECT_TX(sbr + 16 * s2, STAGE_BYTES);
            uint32_t dA = st0 + (uint32_t)s2 * STAGE_BYTES;
            tma2d(dA,         tmA, (t + 2) * 64, bm, sbr + 16 * s2);
            tma2d(dA + 16384, tmB, (t + 2) * 64, bn, sbr + 16 * s2);
        }

#pragma unroll
        for (int kc = 0; kc < 4; kc++) {
            const int pb = kc & 1, nb2 = pb ^ 1;
            if (kc < 3) {
                ldsm_x4(fa[nb2][0], sA + aRowB + xa[kc + 1]);
#pragma unroll
                for (int jp = 0; jp < 4; jp++)
                    ldsm_x4(fb[nb2][jp], sB + bRowB + jp * 2048 + xb[kc + 1]);
#pragma unroll
                for (int i = 1; i < 4; i++)
                    ldsm_x4(fa[nb2][i], sA + aRowB + i * 2048 + xa[kc + 1]);
            } else if (t + 1 < T) {
                const int sn  = (s + 1 == NST) ? 0 : s + 1;
                const int fpn = (s + 1 == NST) ? (fph ^ 1) : fph;
                MBARRIER_WAIT_PARITY(sbr + 16 * sn, fpn);
                const uint32_t nA = st0 + (uint32_t)sn * STAGE_BYTES;
                const uint32_t nB = nA + 16384;
                ldsm_x4(fa[nb2][0], nA + aRowB + xa[0]);
#pragma unroll
                for (int jp = 0; jp < 4; jp++)
                    ldsm_x4(fb[nb2][jp], nB + bRowB + jp * 2048 + xb[0]);
#pragma unroll
                for (int i = 1; i < 4; i++)
                    ldsm_x4(fa[nb2][i], nA + aRowB + i * 2048 + xa[0]);
            }
#pragma unroll
            for (int i = 0; i < 4; i++)
#pragma unroll
                for (int j = 0; j < 8; j++)
                    mma_f16(acc[i][j], fa[pb][i], &fb[pb][j >> 1][(j & 1) * 2]);
        }

        MBARRIER_ARRIVE(sbr + 16 * s + 8);

        if (++s == NST)  { s = 0;  fph ^= 1; }
        if (++s2 == NST) { s2 = 0; eph ^= 1; }
    }

#pragma unroll
    for (int i = 0; i < 4; i++) {
        int gm0 = bm + m0 + i * 16 + r;
#pragma unroll
        for (int j = 0; j < 8; j++) {
            int gn = bn + n0 + j * 8 + 2 * c;
            if (gn >= N) continue;
            float b0 = 0.f, b1 = 0.f;
            if (BIAS) {
                b0 = __half2float(__ldg(&bias[gn]));
                b1 = __half2float(__ldg(&bias[gn + 1]));
            }
            float4 v = acc[i][j];
            float x0 = v.x + b0, x1 = v.y + b1;
            float y0 = v.z + b0, y1 = v.w + b1;
            if (RELU) {
                x0 = fmaxf(x0, 0.f); x1 = fmaxf(x1, 0.f);
                y0 = fmaxf(y0, 0.f); y1 = fmaxf(y1, 0.f);
            }
            if (gm0 < M) {
                CT* p = &C[(size_t)gm0 * ldc + gn];
                if (sizeof(CT) == 2) *(half2*)p = __floats2half2_rn(x0, x1);
                else                 *(float2*)p = make_float2(x0, x1);
            }
            if (gm0 + 8 < M) {
                CT* p = &C[(size_t)(gm0 + 8) * ldc + gn];
                if (sizeof(CT) == 2) *(half2*)p = __floats2half2_rn(y0, y1);
                else                 *(float2*)p = make_float2(y0, y1);
            }
        }
    }
}

// ============================ mega kernel ===================================

__global__ __launch_bounds__(128, 2)
void mega(const __grid_constant__ CUtensorMap mA0, const __grid_constant__ CUtensorMap mB0,
          const __grid_constant__ CUtensorMap mA1, const __grid_constant__ CUtensorMap mB1,
          const __grid_constant__ CUtensorMap mA2, const __grid_constant__ CUtensorMap mB2,
          const __grid_constant__ CUtensorMap mA3, const __grid_constant__ CUtensorMap mB3,
          const float* __restrict__ V1, const float* __restrict__ V2,
          const float* __restrict__ x, float* __restrict__ out)
{
    extern __shared__ uint32_t smu[];
    const int id  = blockIdx.x;
    const int tid = threadIdx.x;

    if (id < P_V1) {
        // ---- prep0: V1 row -> V1h (f16, K-padded)
        const float* s = V1 + (size_t)id * SIZE_M;
        __half* d = g_V1h + (size_t)id * K_PAD;
        for (int p = tid; p < K_PAD / 2; p += 128) {
            int cc = 2 * p;
            float v0 = (cc < SIZE_M)     ? s[cc]     : 0.f;
            float v1 = (cc + 1 < SIZE_M) ? s[cc + 1] : 0.f;
            *(half2*)&d[cc] = __floats2half2_rn(v0, v1);
        }
        __syncthreads();
        if (tid == 0) { __threadfence(); red_rel(&g_pA[id >> 7]); }
    } else if (id < P_V1 + P_V2) {
        // ---- prep1: V2 32x32 transpose tile -> V2T (nb-major ids)
        int q  = id - P_V1;
        int ntile = q / TRN_KB;           // 0..181 (n-block of 32)
        int kbt   = q - ntile * TRN_KB;   // 0..91
        int nb = ntile * 32, kb = kbt * 32;
        float* tt = (float*)smu;          // [32][33]
#pragma unroll
        for (int i = 0; i < 8; i++) {
            int idx = tid + i * 128;
            int kk = idx >> 5, nn = idx & 31;
            int k = kb + kk, n = nb + nn;
            float v = 0.f;
            if (k < SIZE_M && n < SIZE_N) v = V2[(size_t)k * SIZE_N + n];
            tt[kk * 33 + nn] = v;
        }
        __syncthreads();
#pragma unroll
        for (int i = 0; i < 4; i++) {
            int idx = tid + i * 128;
            int nn = idx >> 4, j = idx & 15;
            int n = nb + nn;
            if (n < SIZE_N) {
                half2 h = __floats2half2_rn(tt[2 * j * 33 + nn], tt[(2 * j + 1) * 33 + nn]);
                *(half2*)&g_V2T[(size_t)n * K_PAD + kb + 2 * j] = h;
            }
        }
        __syncthreads();
        if (tid == 0) { __threadfence(); red_rel(&g_pB[ntile >> 2]); }
    } else if (id < PREP_TOT) {
        // ---- prep2: x -> f16 (8 f32 per thread)
        int q = id - (P_V1 + P_V2);
        int i = q * 128 + tid;
        const float4* s4 = (const float4*)x;
        float4 a = s4[2 * i], b = s4[2 * i + 1];
        half2 h0 = __floats2half2_rn(a.x, a.y), h1 = __floats2half2_rn(a.z, a.w);
        half2 h2 = __floats2half2_rn(b.x, b.y), h3 = __floats2half2_rn(b.z, b.w);
        uint4 o;
        o.x = *(uint32_t*)&h0; o.y = *(uint32_t*)&h1;
        o.z = *(uint32_t*)&h2; o.w = *(uint32_t*)&h3;
        ((uint4*)g_xh)[i] = o;
        __syncthreads();
        if (tid == 0) { __threadfence(); red_rel(&g_pX); }
    } else if (id < PREP_TOT + G0_CTAS) {
        // ---- seg0: Vf = V1h @ V2T^T; waits its own prep blocks
        int t = id - PREP_TOT;
        int by = t / 46, bx = t % 46;
        if (tid == 0) {
            spinc(&g_pA[by], by < 45 ? 128 : 34);
            spinc(&g_pB[bx], bx < 45 ? 368 : 184);
            FENCE_PROXY_ASYNC();
        }
        __syncthreads();
        gemm_body<false, false, __half>(smu, &mA0, &mB0, nullptr, g_Vf,
                                        SIZE_N, SIZE_N, K_PAD / 64, SIZE_N, bx, by);
        __syncthreads();
        if (tid == 0) {
            __threadfence();
            if (by < 12) red_rel(&g_cA);
            if (by < 34) red_rel(&g_cB);
            red_rel(&g_cC);
        }
    } else if (id < PREP_TOT + G0_CTAS + L1_CTAS) {
        // ---- seg1: h1 = relu(xh @ W1^T + b1)
        int q = id - (PREP_TOT + G0_CTAS);
        if (tid == 0) {
            spinc(&g_pX, P_X);
            spinc(&g_cA, TGT_A);
            FENCE_PROXY_ASYNC();
        }
        __syncthreads();
        gemm_body<true, true, __half>(smu, &mA1, &mB1, g_Vf + OFF_B1, g_h1,
                                      BATCH, D_H, D_IN / 64, D_H, q & 31, q >> 5);
        __syncthreads();
        if (tid == 0) { __threadfence(); red_rel(&g_c1r[q >> 5]); }
    } else if (id < PREP_TOT + G0_CTAS + L1_CTAS + L2_CTAS) {
        // ---- seg2: h2 = relu(h1 @ W2^T + b2)
        int q = id - (PREP_TOT + G0_CTAS + L1_CTAS);
        if (tid == 0) {
            spinc(&g_cB, TGT_B);
            spinc(&g_c1r[q >> 5], 32);
            FENCE_PROXY_ASYNC();
        }
        __syncthreads();
        gemm_body<true, true, __half>(smu, &mA2, &mB2, g_Vf + OFF_B2, g_h2,
                                      BATCH, D_H, D_H / 64, D_H, q & 31, q >> 5);
        __syncthreads();
        if (tid == 0) { __threadfence(); red_rel(&g_c2r[q >> 5]); }
    } else {
        // ---- seg3: out = h2 @ W3^T + b3
        int q = id - (PREP_TOT + G0_CTAS + L1_CTAS + L2_CTAS);
        if (tid == 0) {
            spinc(&g_cC, G0_CTAS);
            spinc(&g_c2r[q >> 4], 32);
            FENCE_PROXY_ASYNC();
        }
        __syncthreads();
        gemm_body<true, false, float>(smu, &mA3, &mB3, g_Vf + OFF_B3, out,
                                      BATCH, D_OUT, D_H / 64, D_OUT, q & 15, q >> 4);
    }
}

// ============================ zero kernel ===================================

__global__ void zero_counters_kernel() {
    int t = threadIdx.x;
    if (t == 0) { g_cA = 0; g_cB = 0; g_cC = 0; g_pX = 0; }
    if (t < 32) { g_c1r[t] = 0; g_c2r[t] = 0; }
    if (t < 46) { g_pA[t] = 0; g_pB[t] = 0; }
}

// ============================ host side =====================================

typedef CUresult (*tmap_encode_fn)(
    CUtensorMap*, CUtensorMapDataType, cuuint32_t, void*,
    const cuuint64_t*, const cuuint64_t*, const cuuint32_t*, const cuuint32_t*,
    CUtensorMapInterleave, CUtensorMapSwizzle, CUtensorMapL2promotion, CUtensorMapFloatOOBfill);

static void make_map(CUtensorMap* m, void* ptr, uint64_t k_elems, uint64_t rows,
                     uint64_t stride_bytes)
{
    static tmap_encode_fn enc = nullptr;
    if (!enc) {
        cudaDriverEntryPointQueryResult qr;
        cudaGetDriverEntryPointByVersion("cuTensorMapEncodeTiled", (void**)&enc,
                                         12000, cudaEnableDefault, &qr);
    }
    cuuint64_t dims[2]    = {k_elems, rows};
    cuuint64_t strides[1] = {stride_bytes};
    cuuint32_t box[2]     = {64, 128};
    cuuint32_t es[2]      = {1, 1};
    enc(m, CU_TENSOR_MAP_DATA_TYPE_FLOAT16, 2, ptr, dims, strides, box, es,
        CU_TENSOR_MAP_INTERLEAVE_NONE, CU_TENSOR_MAP_SWIZZLE_128B,
        CU_TENSOR_MAP_L2_PROMOTION_L2_128B, CU_TENSOR_MAP_FLOAT_OOB_FILL_NONE);
}

extern "C" void kernel_launch(void* const* d_in, const int* in_sizes, int n_in,
                              void* d_out, int out_size)
{
    const float* x  = (const float*)d_in[0];   // [4096, 2048]
    const float* V1 = (const float*)d_in[1];   // [5794, 2897]
    const float* V2 = (const float*)d_in[2];   // [2897, 5794]
    float* out = (float*)d_out;                // [4096, 2048]

    __half *V1h, *V2T, *xh, *Vf, *h1, *h2;
    cudaGetSymbolAddress((void**)&V1h, g_V1h);
    cudaGetSymbolAddress((void**)&V2T, g_V2T);
    cudaGetSymbolAddress((void**)&xh,  g_xh);
    cudaGetSymbolAddress((void**)&Vf,  g_Vf);
    cudaGetSymbolAddress((void**)&h1,  g_h1);
    cudaGetSymbolAddress((void**)&h2,  g_h2);

    CUtensorMap mA0, mB0, mA1, mB1, mA2, mB2, mA3, mB3;
    make_map(&mA0, V1h,          K_PAD, SIZE_N, (uint64_t)K_PAD * 2);
    make_map(&mB0, V2T,          K_PAD, SIZE_N, (uint64_t)K_PAD * 2);
    make_map(&mA1, xh,           D_IN,  BATCH,  (uint64_t)D_IN * 2);
    make_map(&mB1, Vf + OFF_W1,  D_IN,  D_H,    (uint64_t)D_IN * 2);
    make_map(&mA2, h1,           D_H,   BATCH,  (uint64_t)D_H * 2);
    make_map(&mB2, Vf + OFF_W2,  D_H,   D_H,    (uint64_t)D_H * 2);
    make_map(&mA3, h2,           D_H,   BATCH,  (uint64_t)D_H * 2);
    make_map(&mB3, Vf + OFF_W3,  D_H,   D_OUT,  (uint64_t)D_H * 2);

    cudaFuncSetAttribute(mega, cudaFuncAttributeMaxDynamicSharedMemorySize, SMEM_REQ);

    zero_counters_kernel<<<1, 64>>>();
    mega<<<PREP_TOT + G0_CTAS + L1_CTAS + L2_CTAS + L3_CTAS, 128, SMEM_REQ>>>(
        mA0, mB0, mA1, mB1, mA2, mB2, mA3, mB3, V1, V2, x, out);
}

// round 17
// speedup vs baseline: 1.0847x; 1.0847x over previous
#include <cuda_runtime.h>
#include <cuda.h>
#include <cuda_fp16.h>
#include <cstdint>

// ---------------------------------------------------------------------------
// FeatherNet: separate high-occupancy prep (R13) + mega GEMM launch with
// STAGE-GRANULAR cross-segment pipelining:
//   seg0: Vf = V1@V2 (2116)   releases cA/cB/cC (Vf row-tiles)
//   seg1: h1 (1024)  waits cA;              releases g_f1[by][bx]
//   seg2: h2 (1024)  waits cB + f1[by][t>>1] inside the TMA producer loop;
//                                            releases g_f2[by][bx]
//   seg3: out (512)  waits cC + f2[by][t>>1] inside the producer loop
// Consumers trail producers by ~2 stages instead of a whole CTA (kills the
// ~76us pipeline drain measured in R13).
// ---------------------------------------------------------------------------

#define SIZE_N 5794
#define SIZE_M 2897
#define K_PAD  2944        // 46 * 64
#define BATCH  4096
#define D_IN   2048
#define D_H    4096
#define D_OUT  2048

#define OFF_W1 0
#define OFF_B1 8388608
#define OFF_W2 8392704
#define OFF_B2 25169920
#define OFF_W3 25174016
#define OFF_B3 33562624

#define G0_CTAS 2116       // 46 x 46
#define L1_CTAS 1024       // 32 x 32
#define L2_CTAS 1024
#define L3_CTAS 512        // 32 by x 16 bx
#define TGT_A   552        // 12 Vf row-tiles x 46 (covers W1+b1)
#define TGT_B   1564       // 34 Vf row-tiles x 46 (covers W2+b2)

// prep segmentation (blockDim = 256)
#define TRN_NB    182
#define TRN_TILES (TRN_NB * (K_PAD / 32))   // 16744
#define XCONV_BLK (BATCH * D_IN / 8 / 256)  // 4096

__device__ __align__(256) __half g_V1h[(size_t)SIZE_N * K_PAD];
__device__ __align__(256) __half g_V2T[(size_t)SIZE_N * K_PAD];
__device__ __align__(256) __half g_xh [(size_t)BATCH * D_IN];
__device__ __align__(256) __half g_Vf [(size_t)SIZE_N * SIZE_N];
__device__ __align__(256) __half g_h1 [(size_t)BATCH * D_H];
__device__ __align__(256) __half g_h2 [(size_t)BATCH * D_H];

__device__ uint32_t g_cA, g_cB, g_cC;
__device__ uint32_t g_f1[1024];   // [by][bx] h1 tile-done flags
__device__ uint32_t g_f2[1024];   // [by][bx] h2 tile-done flags

// ============================ PTX helpers ===================================

__device__ __forceinline__ uint32_t smem_u32(const void* p) {
    uint32_t a;
    asm("{ .reg .u64 t; cvta.to.shared.u64 t, %1; cvt.u32.u64 %0, t; }"
        : "=r"(a) : "l"(p));
    return a;
}

#define MBARRIER_INIT(addr, cnt) \
    asm volatile("mbarrier.init.shared.b64 [%0], %1;" \
                 :: "r"((uint32_t)(addr)), "r"((uint32_t)(cnt)) : "memory")

#define MBARRIER_EXPECT_TX(addr, bytes) \
    asm volatile("mbarrier.arrive.expect_tx.shared.b64 _, [%0], %1;" \
                 :: "r"((uint32_t)(addr)), "r"((uint32_t)(bytes)) : "memory")

#define MBARRIER_ARRIVE(addr) \
    asm volatile("mbarrier.arrive.shared.b64 _, [%0];" \
                 :: "r"((uint32_t)(addr)) : "memory")

#define MBARRIER_WAIT_PARITY(addr, par) do {                                         \
    uint32_t _m = (uint32_t)(addr); uint32_t _p = (uint32_t)(par); uint32_t _d;      \
    asm volatile("{\n\t.reg .pred p;\n\t"                                            \
        "mbarrier.try_wait.parity.acquire.cta.shared::cta.b64 p, [%1], %2;\n\t"      \
        "selp.b32 %0, 1, 0, p;\n\t}"                                                 \
        : "=r"(_d) : "r"(_m), "r"(_p) : "memory");                                   \
    if (!_d) {                                                                       \
        asm volatile("{\n\t.reg .pred P1;\n\t"                                       \
            "WL_%=:\n\t"                                                             \
            "mbarrier.try_wait.parity.acquire.cta.shared::cta.b64 P1, [%0], %1, 0x989680;\n\t" \
            "@P1 bra.uni WD_%=;\n\t"                                                 \
            "bra.uni WL_%=;\n\t"                                                     \
            "WD_%=:\n\t}"                                                            \
            :: "r"(_m), "r"(_p) : "memory");                                         \
    }                                                                                \
} while (0)

__device__ __forceinline__ void tma2d(uint32_t dst, const CUtensorMap* m,
                                      int cx, int cy, uint32_t bar) {
    asm volatile(
        "cp.async.bulk.tensor.2d.shared::cta.global.tile.mbarrier::complete_tx::bytes "
        "[%0], [%1, {%2, %3}], [%4];"
        :: "r"(dst), "l"(m), "r"(cx), "r"(cy), "r"(bar) : "memory");
}

__device__ __forceinline__ void mma_f16(float4& d, const uint32_t* a, const uint32_t* b) {
    asm volatile(
        "mma.sync.aligned.m16n8k16.row.col.f32.f16.f16.f32 "
        "{%0,%1,%2,%3}, {%4,%5,%6,%7}, {%8,%9}, {%0,%1,%2,%3};"
        : "+f"(d.x), "+f"(d.y), "+f"(d.z), "+f"(d.w)
        : "r"(a[0]), "r"(a[1]), "r"(a[2]), "r"(a[3]), "r"(b[0]), "r"(b[1]));
}

__device__ __forceinline__ void ldsm_x4(uint32_t* r, uint32_t addr) {
    asm volatile("ldmatrix.sync.aligned.m8n8.x4.shared.b16 {%0,%1,%2,%3}, [%4];"
                 : "=r"(r[0]), "=r"(r[1]), "=r"(r[2]), "=r"(r[3]) : "r"(addr));
}

__device__ __forceinline__ uint32_t ld_acq(const uint32_t* p) {
    uint32_t v;
    asm volatile("ld.acquire.gpu.u32 %0, [%1];" : "=r"(v) : "l"(p) : "memory");
    return v;
}
__device__ __forceinline__ void red_rel(uint32_t* p) {
    asm volatile("red.release.gpu.add.u32 [%0], 1;" :: "l"(p) : "memory");
}
__device__ __forceinline__ void spinc(const uint32_t* p, uint32_t tgt) {
    while (ld_acq(p) < tgt) __nanosleep(128);
}
#define FENCE_PROXY_ASYNC() asm volatile("fence.proxy.async;" ::: "memory")

// ============================ GEMM body =====================================
// aflags: optional per-128-column "A tile ready" flags (one u32 per k-block of
// 128 cols, value 1 when ready). Waited in the TMA producer thread only.

#define NST 3
#define STAGE_BYTES 32768
#define SMEM_REQ 99392

template<bool BIAS, bool RELU, typename CT>
__device__ __forceinline__ void gemm_body(
    uint32_t* smu,
    const CUtensorMap* tmA, const CUtensorMap* tmB,
    const __half* __restrict__ bias, CT* __restrict__ C,
    int M, int N, int T, int ldc, int bx, int by,
    const uint32_t* __restrict__ aflags)
{
    const uint32_t sbr = smem_u32(smu);
    const uint32_t st0 = (sbr + 48 + 1023) & ~1023u;

    const int tid = threadIdx.x;
    const int wid = tid >> 5;
    const int lid = tid & 31;
    const int r   = lid >> 2;
    const int c   = lid & 3;
    const int bm  = by * 128;
    const int bn  = bx * 128;
    const int m0  = (wid & 1) * 64;
    const int n0  = (wid >> 1) * 64;

    if (tid == 0) {
#pragma unroll
        for (int s = 0; s < NST; s++) {
            MBARRIER_INIT(sbr + 16 * s, 1);
            MBARRIER_INIT(sbr + 16 * s + 8, 128);
        }
    }
    __syncthreads();

    const int e    = lid & 7;
    const uint32_t aRowB = (uint32_t)(m0 + ((lid >> 3) & 1) * 8 + e) * 128;
    const uint32_t bRowB = (uint32_t)(n0 + (lid >> 4) * 8 + e) * 128;
    uint32_t xa[4], xb[4];
#pragma unroll
    for (int kc = 0; kc < 4; kc++) {
        xa[kc] = (uint32_t)((((2 * kc + (lid >> 4)) ^ e) & 7) * 16);
        xb[kc] = (uint32_t)((((2 * kc + ((lid >> 3) & 1)) ^ e) & 7) * 16);
    }

    float4 acc[4][8];
#pragma unroll
    for (int i = 0; i < 4; i++)
#pragma unroll
        for (int j = 0; j < 8; j++) acc[i][j] = make_float4(0.f, 0.f, 0.f, 0.f);

    if (tid == 0) {
        if (aflags) { spinc(&aflags[0], 1); FENCE_PROXY_ASYNC(); }  // stages 0,1 use k-block 0
        int npro = T < 2 ? T : 2;
        for (int p = 0; p < npro; p++) {
            MBARRIER_EXPECT_TX(sbr + 16 * p, STAGE_BYTES);
            tma2d(st0 + p * STAGE_BYTES,         tmA, p * 64, bm, sbr + 16 * p);
            tma2d(st0 + p * STAGE_BYTES + 16384, tmB, p * 64, bn, sbr + 16 * p);
        }
    }

    uint32_t fa[2][4][4], fb[2][4][4];

    int s = 0, fph = 0;
    int s2 = 2, eph = 1;

    MBARRIER_WAIT_PARITY(sbr + 0, 0);
    {
        const uint32_t sA = st0, sB = st0 + 16384;
        ldsm_x4(fa[0][0], sA + aRowB + xa[0]);
#pragma unroll
        for (int jp = 0; jp < 4; jp++) ldsm_x4(fb[0][jp], sB + bRowB + jp * 2048 + xb[0]);
#pragma unroll
        for (int i = 1; i < 4; i++)   ldsm_x4(fa[0][i], sA + aRowB + i * 2048 + xa[0]);
    }

    for (int t = 0; t < T; t++) {
        const uint32_t sA = st0 + (uint32_t)s * STAGE_BYTES;
        const uint32_t sB = sA + 16384;

        if (tid == 0 && t + 2 < T) {
            MBARRIER_WAIT_PARITY(sbr + 16 * s2 + 8, eph);
            if (aflags) { spinc(&aflags[(t + 2) >> 1], 1); FENCE_PROXY_ASYNC(); }
            MBARRIER_EXPECT_TX(sbr + 16 * s2, STAGE_BYTES);
            uint32_t dA = st0 + (uint32_t)s2 * STAGE_BYTES;
            tma2d(dA,         tmA, (t + 2) * 64, bm, sbr + 16 * s2);
            tma2d(dA + 16384, tmB, (t + 2) * 64, bn, sbr + 16 * s2);
        }

#pragma unroll
        for (int kc = 0; kc < 4; kc++) {
            const int pb = kc & 1, nb2 = pb ^ 1;
            if (kc < 3) {
                ldsm_x4(fa[nb2][0], sA + aRowB + xa[kc + 1]);
#pragma unroll
                for (int jp = 0; jp < 4; jp++)
                    ldsm_x4(fb[nb2][jp], sB + bRowB + jp * 2048 + xb[kc + 1]);
#pragma unroll
                for (int i = 1; i < 4; i++)
                    ldsm_x4(fa[nb2][i], sA + aRowB + i * 2048 + xa[kc + 1]);
            } else if (t + 1 < T) {
                const int sn  = (s + 1 == NST) ? 0 : s + 1;
                const int fpn = (s + 1 == NST) ? (fph ^ 1) : fph;
                MBARRIER_WAIT_PARITY(sbr + 16 * sn, fpn);
                const uint32_t nA = st0 + (uint32_t)sn * STAGE_BYTES;
                const uint32_t nB = nA + 16384;
                ldsm_x4(fa[nb2][0], nA + aRowB + xa[0]);
#pragma unroll
                for (int jp = 0; jp < 4; jp++)
                    ldsm_x4(fb[nb2][jp], nB + bRowB + jp * 2048 + xb[0]);
#pragma unroll
                for (int i = 1; i < 4; i++)
                    ldsm_x4(fa[nb2][i], nA + aRowB + i * 2048 + xa[0]);
            }
#pragma unroll
            for (int i = 0; i < 4; i++)
#pragma unroll
                for (int j = 0; j < 8; j++)
                    mma_f16(acc[i][j], fa[pb][i], &fb[pb][j >> 1][(j & 1) * 2]);
        }

        MBARRIER_ARRIVE(sbr + 16 * s + 8);

        if (++s == NST)  { s = 0;  fph ^= 1; }
        if (++s2 == NST) { s2 = 0; eph ^= 1; }
    }

#pragma unroll
    for (int i = 0; i < 4; i++) {
        int gm0 = bm + m0 + i * 16 + r;
#pragma unroll
        for (int j = 0; j < 8; j++) {
            int gn = bn + n0 + j * 8 + 2 * c;
            if (gn >= N) continue;
            float b0 = 0.f, b1 = 0.f;
            if (BIAS) {
                b0 = __half2float(__ldg(&bias[gn]));
                b1 = __half2float(__ldg(&bias[gn + 1]));
            }
            float4 v = acc[i][j];
            float x0 = v.x + b0, x1 = v.y + b1;
            float y0 = v.z + b0, y1 = v.w + b1;
            if (RELU) {
                x0 = fmaxf(x0, 0.f); x1 = fmaxf(x1, 0.f);
                y0 = fmaxf(y0, 0.f); y1 = fmaxf(y1, 0.f);
            }
            if (gm0 < M) {
                CT* p = &C[(size_t)gm0 * ldc + gn];
                if (sizeof(CT) == 2) *(half2*)p = __floats2half2_rn(x0, x1);
                else                 *(float2*)p = make_float2(x0, x1);
            }
            if (gm0 + 8 < M) {
                CT* p = &C[(size_t)(gm0 + 8) * ldc + gn];
                if (sizeof(CT) == 2) *(half2*)p = __floats2half2_rn(y0, y1);
                else                 *(float2*)p = make_float2(y0, y1);
            }
        }
    }
}

// ============================ mega kernel ===================================

__global__ __launch_bounds__(128, 2)
void mega(const __grid_constant__ CUtensorMap mA0, const __grid_constant__ CUtensorMap mB0,
          const __grid_constant__ CUtensorMap mA1, const __grid_constant__ CUtensorMap mB1,
          const __grid_constant__ CUtensorMap mA2, const __grid_constant__ CUtensorMap mB2,
          const __grid_constant__ CUtensorMap mA3, const __grid_constant__ CUtensorMap mB3,
          float* __restrict__ out)
{
    extern __shared__ uint32_t smu[];
    const int id  = blockIdx.x;
    const int tid = threadIdx.x;

    if (id < G0_CTAS) {
        int by = id / 46, bx = id % 46;
        gemm_body<false, false, __half>(smu, &mA0, &mB0, nullptr, g_Vf,
                                        SIZE_N, SIZE_N, K_PAD / 64, SIZE_N, bx, by, nullptr);
        __syncthreads();
        if (tid == 0) {
            __threadfence();
            if (by < 12) red_rel(&g_cA);
            if (by < 34) red_rel(&g_cB);
            red_rel(&g_cC);
        }
    } else if (id < G0_CTAS + L1_CTAS) {
        int q = id - G0_CTAS;
        if (tid == 0) { spinc(&g_cA, TGT_A); FENCE_PROXY_ASYNC(); }
        __syncthreads();
        gemm_body<true, true, __half>(smu, &mA1, &mB1, g_Vf + OFF_B1, g_h1,
                                      BATCH, D_H, D_IN / 64, D_H, q & 31, q >> 5, nullptr);
        __syncthreads();
        if (tid == 0) { __threadfence(); red_rel(&g_f1[q]); }
    } else if (id < G0_CTAS + L1_CTAS + L2_CTAS) {
        int q = id - (G0_CTAS + L1_CTAS);
        if (tid == 0) { spinc(&g_cB, TGT_B); FENCE_PROXY_ASYNC(); }
        __syncthreads();
        gemm_body<true, true, __half>(smu, &mA2, &mB2, g_Vf + OFF_B2, g_h2,
                                      BATCH, D_H, D_H / 64, D_H, q & 31, q >> 5,
                                      &g_f1[(q >> 5) * 32]);
        __syncthreads();
        if (tid == 0) { __threadfence(); red_rel(&g_f2[q]); }
    } else {
        int q = id - (G0_CTAS + L1_CTAS + L2_CTAS);
        if (tid == 0) { spinc(&g_cC, G0_CTAS); FENCE_PROXY_ASYNC(); }
        __syncthreads();
        gemm_body<true, false, float>(smu, &mA3, &mB3, g_Vf + OFF_B3, out,
                                      BATCH, D_OUT, D_H / 64, D_OUT, q & 15, q >> 4,
                                      &g_f2[(q >> 4) * 32]);
    }
}

// ============================ prep kernels ==================================

__global__ void zero_counters_kernel() {
    int t = blockIdx.x * blockDim.x + threadIdx.x;
    if (t == 0) { g_cA = 0; g_cB = 0; g_cC = 0; }
    if (t < 1024) { g_f1[t] = 0; g_f2[t] = 0; }
}

__global__ void prep_all(const float* __restrict__ V1, const float* __restrict__ V2,
                         const float* __restrict__ x)
{
    const int id  = blockIdx.x;
    const int tid = threadIdx.x;

    if (id < SIZE_N) {
        const float* s = V1 + (size_t)id * SIZE_M;
        __half* d = g_V1h + (size_t)id * K_PAD;
        for (int p = tid; p < K_PAD / 2; p += 256) {
            int cc = 2 * p;
            float v0 = (cc < SIZE_M)     ? s[cc]     : 0.f;
            float v1 = (cc + 1 < SIZE_M) ? s[cc + 1] : 0.f;
            *(half2*)&d[cc] = __floats2half2_rn(v0, v1);
        }
    } else if (id < SIZE_N + TRN_TILES) {
        int q  = id - SIZE_N;
        int nb = (q % TRN_NB) * 32;
        int kb = (q / TRN_NB) * 32;
        __shared__ float tt[32][33];
#pragma unroll
        for (int i = 0; i < 4; i++) {
            int idx = tid + i * 256;
            int kk = idx >> 5, nn = idx & 31;
            int k = kb + kk, n = nb + nn;
            float v = 0.f;
            if (k < SIZE_M && n < SIZE_N) v = V2[(size_t)k * SIZE_N + n];
            tt[kk][nn] = v;
        }
        __syncthreads();
#pragma unroll
        for (int i = 0; i < 2; i++) {
            int idx = tid + i * 256;
            int nn = idx >> 4, j = idx & 15;
            int n = nb + nn;
            if (n < SIZE_N) {
                half2 h = __floats2half2_rn(tt[2 * j][nn], tt[2 * j + 1][nn]);
                *(half2*)&g_V2T[(size_t)n * K_PAD + kb + 2 * j] = h;
            }
        }
    } else {
        int q = id - (SIZE_N + TRN_TILES);
        int i = q * 256 + tid;
        const float4* s4 = (const float4*)x;
        float4 a = s4[2 * i], b = s4[2 * i + 1];
        half2 h0 = __floats2half2_rn(a.x, a.y), h1 = __floats2half2_rn(a.z, a.w);
        half2 h2 = __floats2half2_rn(b.x, b.y), h3 = __floats2half2_rn(b.z, b.w);
        uint4 o;
        o.x = *(uint32_t*)&h0; o.y = *(uint32_t*)&h1;
        o.z = *(uint32_t*)&h2; o.w = *(uint32_t*)&h3;
        ((uint4*)g_xh)[i] = o;
    }
}

// ============================ host side =====================================

typedef CUresult (*tmap_encode_fn)(
    CUtensorMap*, CUtensorMapDataType, cuuint32_t, void*,
    const cuuint64_t*, const cuuint64_t*, const cuuint32_t*, const cuuint32_t*,
    CUtensorMapInterleave, CUtensorMapSwizzle, CUtensorMapL2promotion, CUtensorMapFloatOOBfill);

static void make_map(CUtensorMap* m, void* ptr, uint64_t k_elems, uint64_t rows,
                     uint64_t stride_bytes)
{
    static tmap_encode_fn enc = nullptr;
    if (!enc) {
        cudaDriverEntryPointQueryResult qr;
        cudaGetDriverEntryPointByVersion("cuTensorMapEncodeTiled", (void**)&enc,
                                         12000, cudaEnableDefault, &qr);
    }
    cuuint64_t dims[2]    = {k_elems, rows};
    cuuint64_t strides[1] = {stride_bytes};
    cuuint32_t box[2]     = {64, 128};
    cuuint32_t es[2]      = {1, 1};
    enc(m, CU_TENSOR_MAP_DATA_TYPE_FLOAT16, 2, ptr, dims, strides, box, es,
        CU_TENSOR_MAP_INTERLEAVE_NONE, CU_TENSOR_MAP_SWIZZLE_128B,
        CU_TENSOR_MAP_L2_PROMOTION_L2_128B, CU_TENSOR_MAP_FLOAT_OOB_FILL_NONE);
}

extern "C" void kernel_launch(void* const* d_in, const int* in_sizes, int n_in,
                              void* d_out, int out_size)
{
    const float* x  = (const float*)d_in[0];   // [4096, 2048]
    const float* V1 = (const float*)d_in[1];   // [5794, 2897]
    const float* V2 = (const float*)d_in[2];   // [2897, 5794]
    float* out = (float*)d_out;                // [4096, 2048]

    __half *V1h, *V2T, *xh, *Vf, *h1, *h2;
    cudaGetSymbolAddress((void**)&V1h, g_V1h);
    cudaGetSymbolAddress((void**)&V2T, g_V2T);
    cudaGetSymbolAddress((void**)&xh,  g_xh);
    cudaGetSymbolAddress((void**)&Vf,  g_Vf);
    cudaGetSymbolAddress((void**)&h1,  g_h1);
    cudaGetSymbolAddress((void**)&h2,  g_h2);

    zero_counters_kernel<<<4, 256>>>();
    prep_all<<<SIZE_N + TRN_TILES + XCONV_BLK, 256>>>(V1, V2, x);

    CUtensorMap mA0, mB0, mA1, mB1, mA2, mB2, mA3, mB3;
    make_map(&mA0, V1h,          K_PAD, SIZE_N, (uint64_t)K_PAD * 2);
    make_map(&mB0, V2T,          K_PAD, SIZE_N, (uint64_t)K_PAD * 2);
    make_map(&mA1, xh,           D_IN,  BATCH,  (uint64_t)D_IN * 2);
    make_map(&mB1, Vf + OFF_W1,  D_IN,  D_H,    (uint64_t)D_IN * 2);
    make_map(&mA2, h1,           D_H,   BATCH,  (uint64_t)D_H * 2);
    make_map(&mB2, Vf + OFF_W2,  D_H,   D_H,    (uint64_t)D_H * 2);
    make_map(&mA3, h2,           D_H,   BATCH,  (uint64_t)D_H * 2);
    make_map(&mB3, Vf + OFF_W3,  D_H,   D_OUT,  (uint64_t)D_H * 2);

    cudaFuncSetAttribute(mega, cudaFuncAttributeMaxDynamicSharedMemorySize, SMEM_REQ);

    mega<<<G0_CTAS + L1_CTAS + L2_CTAS + L3_CTAS, 128, SMEM_REQ>>>(
        mA0, mB0, mA1, mB1, mA2, mB2, mA3, mB3, out);
}